// round 10
// baseline (speedup 1.0000x reference)
#include <cuda_runtime.h>
#include <cuda_bf16.h>

#define NN   50000
#define NBLK 782          // ceil(50000/64)
#define HSZ  132          // fp32 activation smem stride (proj/out kernels)
#define WST  40           // fp32 weight k-slice stride (proj kernel)
#define WFT  136          // fp32 full-weight smem stride (out kernel)
#define BST  144          // bf16 smem stride (lstm): 288B -> conflict-free LDS.64 per phase

// ---------------- device scratch (statics; no runtime allocs) ----------------
__device__ float g_P  [(size_t)NN * 512];   // projected inputs + bias, per layer
__device__ float g_H  [(size_t)NN * 128];   // layer-1 output (post-ReLU)
__device__ float g_Hn [(size_t)NN * 128];   // LSTM final hidden per node
__device__ float g_Wih[512 * 128];          // tf32, k8-permuted (proj)
__device__ __nv_bfloat16 g_WhhB[512 * 128]; // bf16, k16-permuted (lstm)
__device__ float g_Wself [128 * 128];       // tf32, k8-permuted (out)
__device__ float g_Wneigh[128 * 128];
__device__ float g_bsum[512];
__device__ float g_bout[128];

// ---------------- helpers ----------------
__device__ __forceinline__ unsigned tf32u(float f) {
    unsigned u; asm("cvt.rna.tf32.f32 %0, %1;" : "=r"(u) : "f"(f)); return u;
}
__device__ __forceinline__ float tf32f(float f) { return __uint_as_float(tf32u(f)); }

__device__ __forceinline__ float sigf(float x)  { return __fdividef(1.f, 1.f + __expf(-x)); }

__device__ __forceinline__ float tanha(float x) {
    float y; asm("tanh.approx.f32 %0, %1;" : "=f"(y) : "f"(x)); return y;
}
__device__ __forceinline__ float siga(float x) {
    return fmaf(0.5f, tanha(0.5f * x), 0.5f);
}

__device__ __forceinline__ void mma8(float* c, unsigned a0, unsigned a1, unsigned a2,
                                     unsigned a3, unsigned b0, unsigned b1) {
    asm volatile("mma.sync.aligned.m16n8k8.row.col.f32.tf32.tf32.f32 "
                 "{%0,%1,%2,%3}, {%4,%5,%6,%7}, {%8,%9}, {%0,%1,%2,%3};"
                 : "+f"(c[0]), "+f"(c[1]), "+f"(c[2]), "+f"(c[3])
                 : "r"(a0), "r"(a1), "r"(a2), "r"(a3), "r"(b0), "r"(b1));
}
__device__ __forceinline__ void mma16(float* c, unsigned a0, unsigned a1, unsigned a2,
                                      unsigned a3, unsigned b0, unsigned b1) {
    asm volatile("mma.sync.aligned.m16n8k16.row.col.f32.bf16.bf16.f32 "
                 "{%0,%1,%2,%3}, {%4,%5,%6,%7}, {%8,%9}, {%0,%1,%2,%3};"
                 : "+f"(c[0]), "+f"(c[1]), "+f"(c[2]), "+f"(c[3])
                 : "r"(a0), "r"(a1), "r"(a2), "r"(a3), "r"(b0), "r"(b1));
}
__device__ __forceinline__ unsigned packbf2(float hi, float lo) {
    unsigned r; asm("cvt.rn.bf16x2.f32 %0, %1, %2;" : "=r"(r) : "f"(hi), "f"(lo)); return r;
}
__device__ __forceinline__ void cpa16(void* dst, const void* src) {
    unsigned d = (unsigned)__cvta_generic_to_shared(dst);
    asm volatile("cp.async.cg.shared.global [%0], [%1], 16;" :: "r"(d), "l"(src));
}
__device__ __forceinline__ void cpcommit() { asm volatile("cp.async.commit_group;"); }

// k16 permutation: within each 16-block put logical pairs {2t,2t+1},{2t+8,2t+9} adjacent
__device__ __forceinline__ int perm16(int k) {
    return (k & ~15) | ((k & 6) << 1) | ((k & 8) >> 2) | (k & 1);
}

// ---- tf32 helpers for proj ----
__device__ __forceinline__ void stage512(float* buf, const float* __restrict__ W,
                                         int ks, int tid) {
#pragma unroll
    for (int i = 0; i < 8; i++) {
        int idx = tid + i * 512;
        int n = idx >> 3, c = idx & 7;
        cpa16(buf + n * WST + c * 4, W + n * 128 + ks * 32 + c * 4);
    }
    cpcommit();
}
__device__ __forceinline__ void gemm512(float (&acc)[4][4][4], const float* As,
                                        float* d0, float* d1, const float* __restrict__ W,
                                        int rowA, int rowB, int gid, int tig, int cg, int tid) {
    stage512(d0, W, 0, tid);
#pragma unroll
    for (int ks = 0; ks < 4; ks++) {
        const float* cur = (ks & 1) ? d1 : d0;
        if (ks < 3) {
            stage512((ks & 1) ? d0 : d1, W, ks + 1, tid);
            asm volatile("cp.async.wait_group 1;");
        } else {
            asm volatile("cp.async.wait_group 0;");
        }
        __syncthreads();
#pragma unroll
        for (int kc = 0; kc < 4; kc++) {
            int kk = ks * 32 + kc * 8;
            unsigned a0 = tf32u(As[rowA * HSZ + kk + tig]);
            unsigned a1 = tf32u(As[rowB * HSZ + kk + tig]);
            unsigned a2 = tf32u(As[rowA * HSZ + kk + tig + 4]);
            unsigned a3 = tf32u(As[rowB * HSZ + kk + tig + 4]);
#pragma unroll
            for (int g = 0; g < 4; g++)
#pragma unroll
                for (int tt = 0; tt < 4; tt++) {
                    float2 b = *(const float2*)&cur[(g * 128 + cg * 32 + tt * 8 + gid) * WST
                                                    + kc * 8 + 2 * tig];
                    mma8(acc[g][tt], a0, a1, a2, a3,
                         __float_as_uint(b.x), __float_as_uint(b.y));
                }
        }
        __syncthreads();
    }
}

// ---------------- prep ----------------
__global__ void prep_kernel(const float* __restrict__ wih, const float* __restrict__ whh,
                            const float* __restrict__ bih, const float* __restrict__ bhh,
                            const float* __restrict__ wself, const float* __restrict__ wneigh,
                            const float* __restrict__ bo, int hout) {
    int i = blockIdx.x * 256 + threadIdx.x;
    if (i < 512 * 128) {
        int n = i >> 7, k = i & 127;
        int kp = (k & ~7) | ((k & 3) << 1) | ((k >> 2) & 1);  // tf32 k8 perm
        g_Wih[n * 128 + kp] = tf32f(wih[i]);
        g_WhhB[n * 128 + perm16(k)] = __float2bfloat16(whh[i]);
    }
    if (i < hout * 128) {
        int n = i >> 7, k = i & 127;
        int kp = (k & ~7) | ((k & 3) << 1) | ((k >> 2) & 1);
        g_Wself[n * 128 + kp]  = tf32f(wself[i]);
        g_Wneigh[n * 128 + kp] = tf32f(wneigh[i]);
    }
    if (i < 512)  g_bsum[i] = bih[i] + bhh[i];
    if (i < 128 && i < hout) g_bout[i] = bo[i];
}

// ---------------- proj: P = x @ Wih^T + bsum (tf32) ----------------
__global__ void __launch_bounds__(512, 1) proj_kernel(const float* __restrict__ xext, int sel) {
    extern __shared__ float sm[];
    float* xs = sm;
    float* d0 = sm + 64 * HSZ;
    float* d1 = d0 + 512 * WST;
    const float* x = sel ? g_H : xext;
    int tid = threadIdx.x, lane = tid & 31, warp = tid >> 5;
    int wr = warp >> 2, cg = warp & 3, gid = lane >> 2, tig = lane & 3;
    int base = blockIdx.x * 64;
    int rowA = wr * 16 + gid, rowB = rowA + 8;
    bool vA = base + rowA < NN, vB = base + rowB < NN;

#pragma unroll
    for (int i = 0; i < 4; i++) {
        int idx = tid + i * 512;
        int r = idx >> 5, c = idx & 31;
        if (base + r < NN) cpa16(xs + r * HSZ + c * 4, x + (size_t)(base + r) * 128 + c * 4);
    }
    cpcommit();

    float acc[4][4][4];
#pragma unroll
    for (int g = 0; g < 4; g++)
#pragma unroll
        for (int tt = 0; tt < 4; tt++)
#pragma unroll
            for (int s = 0; s < 4; s++) acc[g][tt][s] = 0.f;

    gemm512(acc, xs, d0, d1, g_Wih, rowA, rowB, gid, tig, cg, tid);

    size_t nA = (size_t)(base + rowA) * 512, nB = (size_t)(base + rowB) * 512;
#pragma unroll
    for (int g = 0; g < 4; g++)
#pragma unroll
        for (int tt = 0; tt < 4; tt++) {
            int col = g * 128 + cg * 32 + tt * 8 + 2 * tig;
            float2 bb = *(const float2*)&g_bsum[col];
            if (vA) { float2 v = make_float2(acc[g][tt][0] + bb.x, acc[g][tt][1] + bb.y);
                      *(float2*)&g_P[nA + col] = v; }
            if (vB) { float2 v = make_float2(acc[g][tt][2] + bb.x, acc[g][tt][3] + bb.y);
                      *(float2*)&g_P[nB + col] = v; }
        }
}

// ---------------- lstm: Wn=16 layout, 2-phase m-split pipeline ----------------
__global__ void __launch_bounds__(512, 1) lstm_kernel(const int* __restrict__ nbr) {
    extern __shared__ char smraw[];
    __nv_bfloat16* wsm  = (__nv_bfloat16*)smraw;          // 512 x BST
    __nv_bfloat16* hbuf = wsm + 512 * BST;                // 2 x 64 x BST
    int* snbr = (int*)(hbuf + 2 * 64 * BST);              // 64 x 16

    int tid = threadIdx.x, lane = tid & 31, warp = tid >> 5;
    int gid = lane >> 2, tig = lane & 3;
    int base = blockIdx.x * 64;

    // stage W_hh (bf16, k16-permuted) once
#pragma unroll
    for (int i = 0; i < 16; i++) {
        int idx = tid + i * 512;
        int n = idx >> 4, c = idx & 15;
        cpa16(wsm + n * BST + c * 8, g_WhhB + n * 128 + c * 8);
    }
    cpcommit();
    for (int i = tid; i < 64 * BST / 2; i += 512) ((unsigned*)hbuf)[i] = 0;  // zero h buf 0
#pragma unroll
    for (int i = 0; i < 2; i++) {
        int idx = tid + i * 512;
        int r = idx >> 4;
        snbr[idx] = (base + r < NN) ? nbr[(size_t)(base + r) * 16 + (idx & 15)] : 0;
    }
    asm volatile("cp.async.wait_group 0;");
    __syncthreads();

    const char* wbase = (const char*)wsm;
    int cb = warp * 8 + 2 * tig;                    // this warp's column pair base (per gate)
    int u = warp * 8 + 2 * tig;
    int phys = (u & ~15) | ((u & 6) << 1) | ((u & 8) >> 2);

    float cst[4][4];
#pragma unroll
    for (int m = 0; m < 4; m++)
#pragma unroll
        for (int s = 0; s < 4; s++) cst[m][s] = 0.f;

    float acc[4][4][4];   // [gate][m-tile][frag]
    // pre-gather step 0 gate init from P
#pragma unroll
    for (int m = 0; m < 4; m++) {
        const float* PA = g_P + (size_t)snbr[(m * 16 + gid) * 16 + 0] * 512;
        const float* PB = g_P + (size_t)snbr[(m * 16 + 8 + gid) * 16 + 0] * 512;
#pragma unroll
        for (int g = 0; g < 4; g++) {
            float2 va = *(const float2*)&PA[g * 128 + cb];
            float2 vb = *(const float2*)&PB[g * 128 + cb];
            acc[g][m][0] = va.x; acc[g][m][1] = va.y;
            acc[g][m][2] = vb.x; acc[g][m][3] = vb.y;
        }
    }

    for (int t = 0; t < 16; t++) {
        const char* hc = (const char*)(hbuf + (t & 1) * 64 * BST);
        char*       hn = (char*)(hbuf + ((t + 1) & 1) * 64 * BST);

        // cell update + gather-ahead + h store for one m-tile (pure per-thread work)
        auto cell_m = [&](int m) {
            float hv[4];
#pragma unroll
            for (int s = 0; s < 4; s++) {
                float iv = siga(acc[0][m][s]);
                float fv = siga(acc[1][m][s]);
                float gv = tanha(acc[2][m][s]);
                float ov = siga(acc[3][m][s]);
                float c = fv * cst[m][s] + iv * gv;
                cst[m][s] = c;
                hv[s] = ov * tanha(c);
            }
            if (t < 15) {   // prefetch next step's gate init into freed acc regs
                const float* PA = g_P + (size_t)snbr[(m * 16 + gid) * 16 + t + 1] * 512;
                const float* PB = g_P + (size_t)snbr[(m * 16 + 8 + gid) * 16 + t + 1] * 512;
#pragma unroll
                for (int g = 0; g < 4; g++) {
                    float2 va = *(const float2*)&PA[g * 128 + cb];
                    float2 vb = *(const float2*)&PB[g * 128 + cb];
                    acc[g][m][0] = va.x; acc[g][m][1] = va.y;
                    acc[g][m][2] = vb.x; acc[g][m][3] = vb.y;
                }
            }
            *(unsigned*)(hn + (m * 16 + gid) * (BST * 2) + phys * 2)     = packbf2(hv[1], hv[0]);
            *(unsigned*)(hn + (m * 16 + 8 + gid) * (BST * 2) + phys * 2) = packbf2(hv[3], hv[2]);
        };

        // ---- phase 1: full k-loop for m-tiles 0,1 ----
#pragma unroll
        for (int kc = 0; kc < 8; kc++) {
            uint2 va0 = *(const uint2*)(hc + (0 * 16 + gid) * (BST * 2) + kc * 32 + tig * 8);
            uint2 vb0 = *(const uint2*)(hc + (0 * 16 + 8 + gid) * (BST * 2) + kc * 32 + tig * 8);
            uint2 va1 = *(const uint2*)(hc + (1 * 16 + gid) * (BST * 2) + kc * 32 + tig * 8);
            uint2 vb1 = *(const uint2*)(hc + (1 * 16 + 8 + gid) * (BST * 2) + kc * 32 + tig * 8);
#pragma unroll
            for (int g = 0; g < 4; g++) {
                uint2 b = *(const uint2*)(wbase + (g * 128 + warp * 8 + gid) * (BST * 2)
                                          + kc * 32 + tig * 8);
                mma16(acc[g][0], va0.x, vb0.x, va0.y, vb0.y, b.x, b.y);
                mma16(acc[g][1], va1.x, vb1.x, va1.y, vb1.y, b.x, b.y);
            }
        }

        // ---- phase 2: k-loop for m-tiles 2,3 with cell(0),cell(1) interleaved ----
#pragma unroll
        for (int kc = 0; kc < 8; kc++) {
            uint2 va2 = *(const uint2*)(hc + (2 * 16 + gid) * (BST * 2) + kc * 32 + tig * 8);
            uint2 vb2 = *(const uint2*)(hc + (2 * 16 + 8 + gid) * (BST * 2) + kc * 32 + tig * 8);
            uint2 va3 = *(const uint2*)(hc + (3 * 16 + gid) * (BST * 2) + kc * 32 + tig * 8);
            uint2 vb3 = *(const uint2*)(hc + (3 * 16 + 8 + gid) * (BST * 2) + kc * 32 + tig * 8);
#pragma unroll
            for (int g = 0; g < 4; g++) {
                uint2 b = *(const uint2*)(wbase + (g * 128 + warp * 8 + gid) * (BST * 2)
                                          + kc * 32 + tig * 8);
                mma16(acc[g][2], va2.x, vb2.x, va2.y, vb2.y, b.x, b.y);
                mma16(acc[g][3], va3.x, vb3.x, va3.y, vb3.y, b.x, b.y);
            }
            if (kc == 2) cell_m(0);     // MUFU overlaps remaining mma/LDS
            if (kc == 5) cell_m(1);
        }
        cell_m(2);
        cell_m(3);
        __syncthreads();
    }

    // final hidden in buffer 0; un-permute to g_Hn fp32
    const __nv_bfloat16* hf = hbuf;
    for (int i = tid; i < 64 * 128; i += 512) {
        int r = i >> 7, uu = i & 127;
        if (base + r < NN)
            g_Hn[(size_t)(base + r) * 128 + uu] = __bfloat162float(hf[r * BST + perm16(uu)]);
    }
}

// ---------------- out: o = x@Wself^T + hN@Wneigh^T + b  (+ ReLU / sigmoid) ----------------
template<int HOUT, int ACT>
__global__ void __launch_bounds__(512, 1) out_kernel(const float* __restrict__ xext, int sel,
                                                     float* __restrict__ oext, int osel) {
    extern __shared__ float sm[];
    float* xs = sm;
    float* h2 = xs + 64 * HSZ;
    float* ws = h2 + 64 * HSZ;
    float* wn = ws + HOUT * WFT;
    const float* x = sel ? g_H : xext;
    float* o = osel ? oext : g_H;
    int tid = threadIdx.x, lane = tid & 31, warp = tid >> 5;
    int wr = warp >> 2, cg = warp & 3, gid = lane >> 2, tig = lane & 3;
    int base = blockIdx.x * 64;
    int rowA = wr * 16 + gid, rowB = rowA + 8;
    bool vA = base + rowA < NN, vB = base + rowB < NN;

#pragma unroll
    for (int i = 0; i < 4; i++) {
        int idx = tid + i * 512;
        int r = idx >> 5, c = idx & 31;
        if (base + r < NN) {
            cpa16(xs + r * HSZ + c * 4, x    + (size_t)(base + r) * 128 + c * 4);
            cpa16(h2 + r * HSZ + c * 4, g_Hn + (size_t)(base + r) * 128 + c * 4);
        }
    }
#pragma unroll
    for (int i = 0; i < HOUT * 32 / 512; i++) {
        int idx = tid + i * 512;
        int n = idx >> 5, c = idx & 31;
        cpa16(ws + n * WFT + c * 4, g_Wself  + n * 128 + c * 4);
        cpa16(wn + n * WFT + c * 4, g_Wneigh + n * 128 + c * 4);
    }
    cpcommit();
    asm volatile("cp.async.wait_group 0;");
    __syncthreads();

    constexpr int T = HOUT / 32;
    float acc[T][4];
#pragma unroll
    for (int tt = 0; tt < T; tt++)
#pragma unroll
        for (int s = 0; s < 4; s++) acc[tt][s] = 0.f;

#pragma unroll
    for (int p = 0; p < 2; p++) {
        const float* As = p ? h2 : xs;
        const float* W  = p ? wn : ws;
#pragma unroll
        for (int kc = 0; kc < 16; kc++) {
            int kk = kc * 8;
            unsigned a0 = tf32u(As[rowA * HSZ + kk + tig]);
            unsigned a1 = tf32u(As[rowB * HSZ + kk + tig]);
            unsigned a2 = tf32u(As[rowA * HSZ + kk + tig + 4]);
            unsigned a3 = tf32u(As[rowB * HSZ + kk + tig + 4]);
#pragma unroll
            for (int tt = 0; tt < T; tt++) {
                float2 b = *(const float2*)&W[(cg * (HOUT / 4) + tt * 8 + gid) * WFT
                                              + kk + 2 * tig];
                mma8(acc[tt], a0, a1, a2, a3, __float_as_uint(b.x), __float_as_uint(b.y));
            }
        }
    }
#pragma unroll
    for (int tt = 0; tt < T; tt++)
#pragma unroll
        for (int s = 0; s < 4; s++) {
            int u = cg * (HOUT / 4) + tt * 8 + 2 * tig + (s & 1);
            float v = acc[tt][s] + g_bout[u];
            v = ACT ? sigf(v) : fmaxf(v, 0.f);
            int row = (s < 2) ? rowA : rowB;
            bool vv = (s < 2) ? vA : vB;
            if (vv) o[(size_t)(base + row) * HOUT + u] = v;
        }
}

// ---------------- launch ----------------
extern "C" void kernel_launch(void* const* d_in, const int* in_sizes, int n_in,
                              void* d_out, int out_size) {
    const float* feats = (const float*)d_in[0];
    const int*   nbr   = (const int*)d_in[1];

    const int PSM  = (64 * HSZ + 2 * 512 * WST) * 4;                 // 197632
    const int LSM  = 512 * BST * 2 + 2 * 64 * BST * 2 + 64 * 16 * 4; // 188416
    const int OSM1 = (2 * 64 * HSZ + 2 * 128 * WFT) * 4;             // 206848
    const int OSM2 = (2 * 64 * HSZ + 2 * 64 * WFT) * 4;              // 137216
    cudaFuncSetAttribute(proj_kernel,       cudaFuncAttributeMaxDynamicSharedMemorySize, PSM);
    cudaFuncSetAttribute(lstm_kernel,       cudaFuncAttributeMaxDynamicSharedMemorySize, LSM);
    cudaFuncSetAttribute(out_kernel<128,0>, cudaFuncAttributeMaxDynamicSharedMemorySize, OSM1);
    cudaFuncSetAttribute(out_kernel<64,1>,  cudaFuncAttributeMaxDynamicSharedMemorySize, OSM2);

    dim3 g(NBLK), b(512);

    // layer 1
    prep_kernel<<<256, 256>>>((const float*)d_in[2], (const float*)d_in[3],
                              (const float*)d_in[4], (const float*)d_in[5],
                              (const float*)d_in[6], (const float*)d_in[7],
                              (const float*)d_in[8], 128);
    proj_kernel<<<g, b, PSM>>>(feats, 0);
    lstm_kernel<<<g, b, LSM>>>(nbr);
    out_kernel<128, 0><<<g, b, OSM1>>>(feats, 0, nullptr, 0);

    // layer 2
    prep_kernel<<<256, 256>>>((const float*)d_in[9],  (const float*)d_in[10],
                              (const float*)d_in[11], (const float*)d_in[12],
                              (const float*)d_in[13], (const float*)d_in[14],
                              (const float*)d_in[15], 64);
    proj_kernel<<<g, b, PSM>>>(nullptr, 1);
    lstm_kernel<<<g, b, LSM>>>(nbr);
    out_kernel<64, 1><<<g, b, OSM2>>>(nullptr, 1, (float*)d_out, 1);
}

// round 11
// speedup vs baseline: 1.0278x; 1.0278x over previous
#include <cuda_runtime.h>
#include <cuda_bf16.h>

#define NN   50000
#define NBLK 782          // ceil(50000/64)
#define HSZ  132          // fp32 activation smem stride (out kernel)
#define WFT  136          // fp32 full-weight smem stride (out kernel)
#define BST  144          // bf16 smem stride: 288B -> conflict-free LDS.64 per phase

// ---------------- device scratch (statics; no runtime allocs) ----------------
__device__ __nv_bfloat16 g_P [(size_t)NN * 512];  // projected inputs + bias (bf16, L2-resident)
__device__ float g_H  [(size_t)NN * 128];   // layer-1 output (post-ReLU)
__device__ float g_Hn [(size_t)NN * 128];   // LSTM final hidden per node
__device__ __nv_bfloat16 g_WihB[512 * 128]; // bf16, k16-permuted (proj)
__device__ __nv_bfloat16 g_WhhB[512 * 128]; // bf16, k16-permuted (lstm)
__device__ float g_Wself [128 * 128];       // tf32, k8-permuted (out)
__device__ float g_Wneigh[128 * 128];
__device__ float g_bsum[512];
__device__ float g_bout[128];

// ---------------- helpers ----------------
__device__ __forceinline__ unsigned tf32u(float f) {
    unsigned u; asm("cvt.rna.tf32.f32 %0, %1;" : "=r"(u) : "f"(f)); return u;
}
__device__ __forceinline__ float tf32f(float f) { return __uint_as_float(tf32u(f)); }

__device__ __forceinline__ float sigf(float x)  { return __fdividef(1.f, 1.f + __expf(-x)); }

__device__ __forceinline__ void mma8(float* c, unsigned a0, unsigned a1, unsigned a2,
                                     unsigned a3, unsigned b0, unsigned b1) {
    asm volatile("mma.sync.aligned.m16n8k8.row.col.f32.tf32.tf32.f32 "
                 "{%0,%1,%2,%3}, {%4,%5,%6,%7}, {%8,%9}, {%0,%1,%2,%3};"
                 : "+f"(c[0]), "+f"(c[1]), "+f"(c[2]), "+f"(c[3])
                 : "r"(a0), "r"(a1), "r"(a2), "r"(a3), "r"(b0), "r"(b1));
}
__device__ __forceinline__ void mma16(float* c, unsigned a0, unsigned a1, unsigned a2,
                                      unsigned a3, unsigned b0, unsigned b1) {
    asm volatile("mma.sync.aligned.m16n8k16.row.col.f32.bf16.bf16.f32 "
                 "{%0,%1,%2,%3}, {%4,%5,%6,%7}, {%8,%9}, {%0,%1,%2,%3};"
                 : "+f"(c[0]), "+f"(c[1]), "+f"(c[2]), "+f"(c[3])
                 : "r"(a0), "r"(a1), "r"(a2), "r"(a3), "r"(b0), "r"(b1));
}
__device__ __forceinline__ unsigned packbf2(float hi, float lo) {
    unsigned r; asm("cvt.rn.bf16x2.f32 %0, %1, %2;" : "=r"(r) : "f"(hi), "f"(lo)); return r;
}
// packed bf16x2 math (sm_90+)
__device__ __forceinline__ unsigned mul2(unsigned a, unsigned b) {
    unsigned d; asm("mul.rn.bf16x2 %0,%1,%2;" : "=r"(d) : "r"(a), "r"(b)); return d;
}
__device__ __forceinline__ unsigned fma2(unsigned a, unsigned b, unsigned c) {
    unsigned d; asm("fma.rn.bf16x2 %0,%1,%2,%3;" : "=r"(d) : "r"(a), "r"(b), "r"(c)); return d;
}
__device__ __forceinline__ unsigned tanh2(unsigned a) {
    unsigned d; asm("tanh.approx.bf16x2 %0,%1;" : "=r"(d) : "r"(a)); return d;
}
__device__ __forceinline__ unsigned sig2(unsigned x) {   // 0.5*tanh(0.5x)+0.5, packed
    const unsigned H = 0x3F003F00u;
    return fma2(tanh2(mul2(x, H)), H, H);
}
__device__ __forceinline__ float lo2f(unsigned u) { return __uint_as_float(u << 16); }
__device__ __forceinline__ float hi2f(unsigned u) { return __uint_as_float(u & 0xFFFF0000u); }

__device__ __forceinline__ void cpa16(void* dst, const void* src) {
    unsigned d = (unsigned)__cvta_generic_to_shared(dst);
    asm volatile("cp.async.cg.shared.global [%0], [%1], 16;" :: "r"(d), "l"(src));
}
__device__ __forceinline__ void cpcommit() { asm volatile("cp.async.commit_group;"); }

// k16 permutation: within each 16-block put logical pairs {2t,2t+1},{2t+8,2t+9} adjacent
__device__ __forceinline__ int perm16(int k) {
    return (k & ~15) | ((k & 6) << 1) | ((k & 8) >> 2) | (k & 1);
}

// ---------------- prep ----------------
__global__ void prep_kernel(const float* __restrict__ wih, const float* __restrict__ whh,
                            const float* __restrict__ bih, const float* __restrict__ bhh,
                            const float* __restrict__ wself, const float* __restrict__ wneigh,
                            const float* __restrict__ bo, int hout) {
    int i = blockIdx.x * 256 + threadIdx.x;
    if (i < 512 * 128) {
        int n = i >> 7, k = i & 127;
        g_WihB[n * 128 + perm16(k)] = __float2bfloat16(wih[i]);
        g_WhhB[n * 128 + perm16(k)] = __float2bfloat16(whh[i]);
    }
    if (i < hout * 128) {
        int n = i >> 7, k = i & 127;
        int kp = (k & ~7) | ((k & 3) << 1) | ((k >> 2) & 1);   // tf32 k8 perm
        g_Wself[n * 128 + kp]  = tf32f(wself[i]);
        g_Wneigh[n * 128 + kp] = tf32f(wneigh[i]);
    }
    if (i < 512)  g_bsum[i] = bih[i] + bhh[i];
    if (i < 128 && i < hout) g_bout[i] = bo[i];
}

// ---------------- proj: P = bf16(x @ Wih^T + bsum), single k-pass, W smem-resident ----
__global__ void __launch_bounds__(512, 1) proj_kernel(const float* __restrict__ xext, int sel) {
    extern __shared__ char smraw[];
    __nv_bfloat16* wsm = (__nv_bfloat16*)smraw;               // 512 x BST
    __nv_bfloat16* xs  = wsm + 512 * BST;                     // 64 x BST
    const float* x = sel ? g_H : xext;

    int tid = threadIdx.x, lane = tid & 31, warp = tid >> 5;
    int gid = lane >> 2, tig = lane & 3;
    int base = blockIdx.x * 64;
    int cb = warp * 8 + 2 * tig;

    // stage W_ih (bf16, k16-permuted) via cp.async
#pragma unroll
    for (int i = 0; i < 16; i++) {
        int idx = tid + i * 512;
        int n = idx >> 4, c = idx & 15;
        cpa16(wsm + n * BST + c * 8, g_WihB + n * 128 + c * 8);
    }
    cpcommit();

    // load+convert x tile: thread handles row tid>>3, 8 float2 pairs
    {
        int r = tid >> 3, c0 = (tid & 7) * 16;
        const float* xr = x + (size_t)(base + r) * 128;
        bool v = base + r < NN;
#pragma unroll
        for (int p = 0; p < 8; p++) {
            int col = c0 + 2 * p;
            float2 vv = v ? *(const float2*)&xr[col] : make_float2(0.f, 0.f);
            *(unsigned*)((char*)xs + r * (BST * 2) + perm16(col) * 2) = packbf2(vv.y, vv.x);
        }
    }
    asm volatile("cp.async.wait_group 0;");
    __syncthreads();

    float acc[4][4][4];
#pragma unroll
    for (int g = 0; g < 4; g++)
#pragma unroll
        for (int m = 0; m < 4; m++)
#pragma unroll
            for (int s = 0; s < 4; s++) acc[g][m][s] = 0.f;

    const char* xsb = (const char*)xs;
    const char* wb  = (const char*)wsm;
#pragma unroll
    for (int kc = 0; kc < 8; kc++) {
        uint2 va[4], vb[4];
#pragma unroll
        for (int m = 0; m < 4; m++) {
            va[m] = *(const uint2*)(xsb + (m * 16 + gid) * (BST * 2) + kc * 32 + tig * 8);
            vb[m] = *(const uint2*)(xsb + (m * 16 + 8 + gid) * (BST * 2) + kc * 32 + tig * 8);
        }
#pragma unroll
        for (int g = 0; g < 4; g++) {
            uint2 b = *(const uint2*)(wb + (g * 128 + warp * 8 + gid) * (BST * 2)
                                      + kc * 32 + tig * 8);
#pragma unroll
            for (int m = 0; m < 4; m++)
                mma16(acc[g][m], va[m].x, vb[m].x, va[m].y, vb[m].y, b.x, b.y);
        }
    }

    // epilogue: add bias, store bf16x2 pairs
#pragma unroll
    for (int m = 0; m < 4; m++) {
        int rA = base + m * 16 + gid, rB = rA + 8;
        bool vA = rA < NN, vB = rB < NN;
        size_t nA = (size_t)rA * 512, nB = (size_t)rB * 512;
#pragma unroll
        for (int g = 0; g < 4; g++) {
            int col = g * 128 + cb;
            float2 bb = *(const float2*)&g_bsum[col];
            if (vA) *(unsigned*)&g_P[nA + col] =
                        packbf2(acc[g][m][1] + bb.y, acc[g][m][0] + bb.x);
            if (vB) *(unsigned*)&g_P[nB + col] =
                        packbf2(acc[g][m][3] + bb.y, acc[g][m][2] + bb.x);
        }
    }
}

// ---------------- lstm: R9 structure + bf16 P gathers + packed bf16x2 activations -----
__global__ void __launch_bounds__(512, 1) lstm_kernel(const int* __restrict__ nbr) {
    extern __shared__ char smraw[];
    __nv_bfloat16* wsm  = (__nv_bfloat16*)smraw;          // 512 x BST
    __nv_bfloat16* hbuf = wsm + 512 * BST;                // 2 x 64 x BST
    int* snbr = (int*)(hbuf + 2 * 64 * BST);              // 64 x 16

    int tid = threadIdx.x, lane = tid & 31, warp = tid >> 5;
    int gid = lane >> 2, tig = lane & 3;
    int base = blockIdx.x * 64;

    // stage W_hh (bf16, k16-permuted) once
#pragma unroll
    for (int i = 0; i < 16; i++) {
        int idx = tid + i * 512;
        int n = idx >> 4, c = idx & 15;
        cpa16(wsm + n * BST + c * 8, g_WhhB + n * 128 + c * 8);
    }
    cpcommit();
    for (int i = tid; i < 64 * BST / 2; i += 512) ((unsigned*)hbuf)[i] = 0;  // zero h buf 0
#pragma unroll
    for (int i = 0; i < 2; i++) {
        int idx = tid + i * 512;
        int r = idx >> 4;
        snbr[idx] = (base + r < NN) ? nbr[(size_t)(base + r) * 16 + (idx & 15)] : 0;
    }
    asm volatile("cp.async.wait_group 0;");
    __syncthreads();

    const char* wbase = (const char*)wsm;
    int cb = warp * 8 + 2 * tig;                    // column pair base (per gate)
    int phys = (cb & ~15) | ((cb & 6) << 1) | ((cb & 8) >> 2);

    float cst[4][4];
#pragma unroll
    for (int m = 0; m < 4; m++)
#pragma unroll
        for (int s = 0; s < 4; s++) cst[m][s] = 0.f;

    float acc[4][4][4];   // [gate][m-tile][frag]
    // pre-gather step 0 gate init from bf16 P
#pragma unroll
    for (int m = 0; m < 4; m++) {
        const __nv_bfloat16* PA = g_P + (size_t)snbr[(m * 16 + gid) * 16 + 0] * 512;
        const __nv_bfloat16* PB = g_P + (size_t)snbr[(m * 16 + 8 + gid) * 16 + 0] * 512;
#pragma unroll
        for (int g = 0; g < 4; g++) {
            unsigned ua = *(const unsigned*)(PA + g * 128 + cb);
            unsigned ub = *(const unsigned*)(PB + g * 128 + cb);
            acc[g][m][0] = lo2f(ua); acc[g][m][1] = hi2f(ua);
            acc[g][m][2] = lo2f(ub); acc[g][m][3] = hi2f(ub);
        }
    }

    for (int t = 0; t < 16; t++) {
        const char* hc = (const char*)(hbuf + (t & 1) * 64 * BST);
        char*       hn = (char*)(hbuf + ((t + 1) & 1) * 64 * BST);

        // acc += h @ Whh^T  (bf16 m16n8k16)
#pragma unroll
        for (int kc = 0; kc < 8; kc++) {
            uint2 va[4], vb[4];
#pragma unroll
            for (int m = 0; m < 4; m++) {
                va[m] = *(const uint2*)(hc + (m * 16 + gid) * (BST * 2) + kc * 32 + tig * 8);
                vb[m] = *(const uint2*)(hc + (m * 16 + 8 + gid) * (BST * 2) + kc * 32 + tig * 8);
            }
#pragma unroll
            for (int g = 0; g < 4; g++) {
                uint2 b = *(const uint2*)(wbase + (g * 128 + warp * 8 + gid) * (BST * 2)
                                          + kc * 32 + tig * 8);
#pragma unroll
                for (int m = 0; m < 4; m++)
                    mma16(acc[g][m], va[m].x, vb[m].x, va[m].y, vb[m].y, b.x, b.y);
            }
        }

        // packed cell update + gather-ahead + bf16x2 h store
#pragma unroll
        for (int m = 0; m < 4; m++) {
            unsigned xp[4][2];
#pragma unroll
            for (int g = 0; g < 4; g++) {
                xp[g][0] = packbf2(acc[g][m][1], acc[g][m][0]);
                xp[g][1] = packbf2(acc[g][m][3], acc[g][m][2]);
            }
            if (t < 15) {   // prefetch next step's gate init into freed acc regs
                const __nv_bfloat16* PA =
                    g_P + (size_t)snbr[(m * 16 + gid) * 16 + t + 1] * 512;
                const __nv_bfloat16* PB =
                    g_P + (size_t)snbr[(m * 16 + 8 + gid) * 16 + t + 1] * 512;
#pragma unroll
                for (int g = 0; g < 4; g++) {
                    unsigned ua = *(const unsigned*)(PA + g * 128 + cb);
                    unsigned ub = *(const unsigned*)(PB + g * 128 + cb);
                    acc[g][m][0] = lo2f(ua); acc[g][m][1] = hi2f(ua);
                    acc[g][m][2] = lo2f(ub); acc[g][m][3] = hi2f(ub);
                }
            }
#pragma unroll
            for (int p = 0; p < 2; p++) {
                unsigned ip = sig2(xp[0][p]);
                unsigned fp = sig2(xp[1][p]);
                unsigned gp = tanh2(xp[2][p]);
                unsigned op = sig2(xp[3][p]);
                unsigned ig = mul2(ip, gp);
                float c0 = fmaf(lo2f(fp), cst[m][2 * p],     lo2f(ig));
                float c1 = fmaf(hi2f(fp), cst[m][2 * p + 1], hi2f(ig));
                cst[m][2 * p] = c0; cst[m][2 * p + 1] = c1;
                unsigned hx = mul2(op, tanh2(packbf2(c1, c0)));
                int row = p ? (m * 16 + 8 + gid) : (m * 16 + gid);
                *(unsigned*)(hn + row * (BST * 2) + phys * 2) = hx;
            }
        }
        __syncthreads();
    }

    // final hidden in buffer 0; un-permute to g_Hn fp32
    const __nv_bfloat16* hf = hbuf;
    for (int i = tid; i < 64 * 128; i += 512) {
        int r = i >> 7, uu = i & 127;
        if (base + r < NN)
            g_Hn[(size_t)(base + r) * 128 + uu] = __bfloat162float(hf[r * BST + perm16(uu)]);
    }
}

// ---------------- out: o = x@Wself^T + hN@Wneigh^T + b  (+ ReLU / sigmoid) ----------------
template<int HOUT, int ACT>
__global__ void __launch_bounds__(512, 1) out_kernel(const float* __restrict__ xext, int sel,
                                                     float* __restrict__ oext, int osel) {
    extern __shared__ float sm[];
    float* xs = sm;
    float* h2 = xs + 64 * HSZ;
    float* ws = h2 + 64 * HSZ;
    float* wn = ws + HOUT * WFT;
    const float* x = sel ? g_H : xext;
    float* o = osel ? oext : g_H;
    int tid = threadIdx.x, lane = tid & 31, warp = tid >> 5;
    int wr = warp >> 2, cg = warp & 3, gid = lane >> 2, tig = lane & 3;
    int base = blockIdx.x * 64;
    int rowA = wr * 16 + gid, rowB = rowA + 8;
    bool vA = base + rowA < NN, vB = base + rowB < NN;

#pragma unroll
    for (int i = 0; i < 4; i++) {
        int idx = tid + i * 512;
        int r = idx >> 5, c = idx & 31;
        if (base + r < NN) {
            cpa16(xs + r * HSZ + c * 4, x    + (size_t)(base + r) * 128 + c * 4);
            cpa16(h2 + r * HSZ + c * 4, g_Hn + (size_t)(base + r) * 128 + c * 4);
        }
    }
#pragma unroll
    for (int i = 0; i < HOUT * 32 / 512; i++) {
        int idx = tid + i * 512;
        int n = idx >> 5, c = idx & 31;
        cpa16(ws + n * WFT + c * 4, g_Wself  + n * 128 + c * 4);
        cpa16(wn + n * WFT + c * 4, g_Wneigh + n * 128 + c * 4);
    }
    cpcommit();
    asm volatile("cp.async.wait_group 0;");
    __syncthreads();

    constexpr int T = HOUT / 32;
    float acc[T][4];
#pragma unroll
    for (int tt = 0; tt < T; tt++)
#pragma unroll
        for (int s = 0; s < 4; s++) acc[tt][s] = 0.f;

#pragma unroll
    for (int p = 0; p < 2; p++) {
        const float* As = p ? h2 : xs;
        const float* W  = p ? wn : ws;
#pragma unroll
        for (int kc = 0; kc < 16; kc++) {
            int kk = kc * 8;
            unsigned a0 = tf32u(As[rowA * HSZ + kk + tig]);
            unsigned a1 = tf32u(As[rowB * HSZ + kk + tig]);
            unsigned a2 = tf32u(As[rowA * HSZ + kk + tig + 4]);
            unsigned a3 = tf32u(As[rowB * HSZ + kk + tig + 4]);
#pragma unroll
            for (int tt = 0; tt < T; tt++) {
                float2 b = *(const float2*)&W[(cg * (HOUT / 4) + tt * 8 + gid) * WFT
                                              + kk + 2 * tig];
                mma8(acc[tt], a0, a1, a2, a3, __float_as_uint(b.x), __float_as_uint(b.y));
            }
        }
    }
#pragma unroll
    for (int tt = 0; tt < T; tt++)
#pragma unroll
        for (int s = 0; s < 4; s++) {
            int u = cg * (HOUT / 4) + tt * 8 + 2 * tig + (s & 1);
            float v = acc[tt][s] + g_bout[u];
            v = ACT ? sigf(v) : fmaxf(v, 0.f);
            int row = (s < 2) ? rowA : rowB;
            bool vv = (s < 2) ? vA : vB;
            if (vv) o[(size_t)(base + row) * HOUT + u] = v;
        }
}

// ---------------- launch ----------------
extern "C" void kernel_launch(void* const* d_in, const int* in_sizes, int n_in,
                              void* d_out, int out_size) {
    const float* feats = (const float*)d_in[0];
    const int*   nbr   = (const int*)d_in[1];

    const int PSM  = (512 * BST + 64 * BST) * 2;                     // 165888
    const int LSM  = 512 * BST * 2 + 2 * 64 * BST * 2 + 64 * 16 * 4; // 188416
    const int OSM1 = (2 * 64 * HSZ + 2 * 128 * WFT) * 4;             // 206848
    const int OSM2 = (2 * 64 * HSZ + 2 * 64 * WFT) * 4;              // 137216
    cudaFuncSetAttribute(proj_kernel,       cudaFuncAttributeMaxDynamicSharedMemorySize, PSM);
    cudaFuncSetAttribute(lstm_kernel,       cudaFuncAttributeMaxDynamicSharedMemorySize, LSM);
    cudaFuncSetAttribute(out_kernel<128,0>, cudaFuncAttributeMaxDynamicSharedMemorySize, OSM1);
    cudaFuncSetAttribute(out_kernel<64,1>,  cudaFuncAttributeMaxDynamicSharedMemorySize, OSM2);

    dim3 g(NBLK), b(512);

    // layer 1
    prep_kernel<<<256, 256>>>((const float*)d_in[2], (const float*)d_in[3],
                              (const float*)d_in[4], (const float*)d_in[5],
                              (const float*)d_in[6], (const float*)d_in[7],
                              (const float*)d_in[8], 128);
    proj_kernel<<<g, b, PSM>>>(feats, 0);
    lstm_kernel<<<g, b, LSM>>>(nbr);
    out_kernel<128, 0><<<g, b, OSM1>>>(feats, 0, nullptr, 0);

    // layer 2
    prep_kernel<<<256, 256>>>((const float*)d_in[9],  (const float*)d_in[10],
                              (const float*)d_in[11], (const float*)d_in[12],
                              (const float*)d_in[13], (const float*)d_in[14],
                              (const float*)d_in[15], 64);
    proj_kernel<<<g, b, PSM>>>(nullptr, 1);
    lstm_kernel<<<g, b, LSM>>>(nbr);
    out_kernel<64, 1><<<g, b, OSM2>>>(nullptr, 1, (float*)d_out, 1);
}

// round 12
// speedup vs baseline: 1.0456x; 1.0173x over previous
#include <cuda_runtime.h>
#include <cuda_bf16.h>

#define NN   50000
#define NBLK 782          // ceil(50000/64)
#define HSZ  132          // fp32 activation smem stride (out kernel)
#define WFT  136          // fp32 full-weight smem stride (out kernel)
#define BST  144          // bf16 smem stride: 288B -> conflict-free LDS.64 per phase

// ---------------- device scratch (statics; no runtime allocs) ----------------
__device__ __nv_bfloat16 g_P [(size_t)NN * 512];  // projected inputs + bias (bf16, L2-resident)
__device__ float g_H  [(size_t)NN * 128];   // layer-1 output (post-ReLU)
__device__ float g_Hn [(size_t)NN * 128];   // LSTM final hidden per node
__device__ __nv_bfloat16 g_WihB[512 * 128]; // bf16, k16-permuted (proj)
__device__ __nv_bfloat16 g_WhhB[512 * 128]; // bf16, k16-permuted (lstm)
__device__ float g_Wself [128 * 128];       // tf32, k8-permuted (out)
__device__ float g_Wneigh[128 * 128];
__device__ float g_bsum[512];
__device__ float g_bout[128];

// ---------------- helpers ----------------
__device__ __forceinline__ unsigned tf32u(float f) {
    unsigned u; asm("cvt.rna.tf32.f32 %0, %1;" : "=r"(u) : "f"(f)); return u;
}
__device__ __forceinline__ float tf32f(float f) { return __uint_as_float(tf32u(f)); }

__device__ __forceinline__ float sigf(float x)  { return __fdividef(1.f, 1.f + __expf(-x)); }

__device__ __forceinline__ float tanha(float x) {
    float y; asm("tanh.approx.f32 %0, %1;" : "=f"(y) : "f"(x)); return y;
}
__device__ __forceinline__ float siga(float x) {
    return fmaf(0.5f, tanha(0.5f * x), 0.5f);
}

__device__ __forceinline__ void mma8(float* c, unsigned a0, unsigned a1, unsigned a2,
                                     unsigned a3, unsigned b0, unsigned b1) {
    asm volatile("mma.sync.aligned.m16n8k8.row.col.f32.tf32.tf32.f32 "
                 "{%0,%1,%2,%3}, {%4,%5,%6,%7}, {%8,%9}, {%0,%1,%2,%3};"
                 : "+f"(c[0]), "+f"(c[1]), "+f"(c[2]), "+f"(c[3])
                 : "r"(a0), "r"(a1), "r"(a2), "r"(a3), "r"(b0), "r"(b1));
}
__device__ __forceinline__ void mma16(float* c, unsigned a0, unsigned a1, unsigned a2,
                                      unsigned a3, unsigned b0, unsigned b1) {
    asm volatile("mma.sync.aligned.m16n8k16.row.col.f32.bf16.bf16.f32 "
                 "{%0,%1,%2,%3}, {%4,%5,%6,%7}, {%8,%9}, {%0,%1,%2,%3};"
                 : "+f"(c[0]), "+f"(c[1]), "+f"(c[2]), "+f"(c[3])
                 : "r"(a0), "r"(a1), "r"(a2), "r"(a3), "r"(b0), "r"(b1));
}
__device__ __forceinline__ unsigned packbf2(float hi, float lo) {
    unsigned r; asm("cvt.rn.bf16x2.f32 %0, %1, %2;" : "=r"(r) : "f"(hi), "f"(lo)); return r;
}
__device__ __forceinline__ float lo2f(unsigned u) { return __uint_as_float(u << 16); }
__device__ __forceinline__ float hi2f(unsigned u) { return __uint_as_float(u & 0xFFFF0000u); }

__device__ __forceinline__ void cpa16(void* dst, const void* src) {
    unsigned d = (unsigned)__cvta_generic_to_shared(dst);
    asm volatile("cp.async.cg.shared.global [%0], [%1], 16;" :: "r"(d), "l"(src));
}
__device__ __forceinline__ void cpcommit() { asm volatile("cp.async.commit_group;"); }

// k16 permutation: within each 16-block put logical pairs {2t,2t+1},{2t+8,2t+9} adjacent
__device__ __forceinline__ int perm16(int k) {
    return (k & ~15) | ((k & 6) << 1) | ((k & 8) >> 2) | (k & 1);
}

// ---------------- prep ----------------
__global__ void prep_kernel(const float* __restrict__ wih, const float* __restrict__ whh,
                            const float* __restrict__ bih, const float* __restrict__ bhh,
                            const float* __restrict__ wself, const float* __restrict__ wneigh,
                            const float* __restrict__ bo, int hout) {
    int i = blockIdx.x * 256 + threadIdx.x;
    if (i < 512 * 128) {
        int n = i >> 7, k = i & 127;
        g_WihB[n * 128 + perm16(k)] = __float2bfloat16(wih[i]);
        g_WhhB[n * 128 + perm16(k)] = __float2bfloat16(whh[i]);
    }
    if (i < hout * 128) {
        int n = i >> 7, k = i & 127;
        int kp = (k & ~7) | ((k & 3) << 1) | ((k >> 2) & 1);   // tf32 k8 perm
        g_Wself[n * 128 + kp]  = tf32f(wself[i]);
        g_Wneigh[n * 128 + kp] = tf32f(wneigh[i]);
    }
    if (i < 512)  g_bsum[i] = bih[i] + bhh[i];
    if (i < 128 && i < hout) g_bout[i] = bo[i];
}

// ---------------- proj: P = bf16(x @ Wih^T + bsum), single k-pass, W smem-resident ----
__global__ void __launch_bounds__(512, 1) proj_kernel(const float* __restrict__ xext, int sel) {
    extern __shared__ char smraw[];
    __nv_bfloat16* wsm = (__nv_bfloat16*)smraw;               // 512 x BST
    __nv_bfloat16* xs  = wsm + 512 * BST;                     // 64 x BST
    const float* x = sel ? g_H : xext;

    int tid = threadIdx.x, lane = tid & 31, warp = tid >> 5;
    int gid = lane >> 2, tig = lane & 3;
    int base = blockIdx.x * 64;
    int cb = warp * 8 + 2 * tig;

    // stage W_ih (bf16, k16-permuted) via cp.async
#pragma unroll
    for (int i = 0; i < 16; i++) {
        int idx = tid + i * 512;
        int n = idx >> 4, c = idx & 15;
        cpa16(wsm + n * BST + c * 8, g_WihB + n * 128 + c * 8);
    }
    cpcommit();

    // load+convert x tile: thread handles row tid>>3, 8 float2 pairs
    {
        int r = tid >> 3, c0 = (tid & 7) * 16;
        const float* xr = x + (size_t)(base + r) * 128;
        bool v = base + r < NN;
#pragma unroll
        for (int p = 0; p < 8; p++) {
            int col = c0 + 2 * p;
            float2 vv = v ? *(const float2*)&xr[col] : make_float2(0.f, 0.f);
            *(unsigned*)((char*)xs + r * (BST * 2) + perm16(col) * 2) = packbf2(vv.y, vv.x);
        }
    }
    asm volatile("cp.async.wait_group 0;");
    __syncthreads();

    float acc[4][4][4];
#pragma unroll
    for (int g = 0; g < 4; g++)
#pragma unroll
        for (int m = 0; m < 4; m++)
#pragma unroll
            for (int s = 0; s < 4; s++) acc[g][m][s] = 0.f;

    const char* xsb = (const char*)xs;
    const char* wb  = (const char*)wsm;
#pragma unroll
    for (int kc = 0; kc < 8; kc++) {
        uint2 va[4], vb[4];
#pragma unroll
        for (int m = 0; m < 4; m++) {
            va[m] = *(const uint2*)(xsb + (m * 16 + gid) * (BST * 2) + kc * 32 + tig * 8);
            vb[m] = *(const uint2*)(xsb + (m * 16 + 8 + gid) * (BST * 2) + kc * 32 + tig * 8);
        }
#pragma unroll
        for (int g = 0; g < 4; g++) {
            uint2 b = *(const uint2*)(wb + (g * 128 + warp * 8 + gid) * (BST * 2)
                                      + kc * 32 + tig * 8);
#pragma unroll
            for (int m = 0; m < 4; m++)
                mma16(acc[g][m], va[m].x, vb[m].x, va[m].y, vb[m].y, b.x, b.y);
        }
    }

    // epilogue: add bias, store bf16x2 pairs
#pragma unroll
    for (int m = 0; m < 4; m++) {
        int rA = base + m * 16 + gid, rB = rA + 8;
        bool vA = rA < NN, vB = rB < NN;
        size_t nA = (size_t)rA * 512, nB = (size_t)rB * 512;
#pragma unroll
        for (int g = 0; g < 4; g++) {
            int col = g * 128 + cb;
            float2 bb = *(const float2*)&g_bsum[col];
            if (vA) *(unsigned*)&g_P[nA + col] =
                        packbf2(acc[g][m][1] + bb.y, acc[g][m][0] + bb.x);
            if (vB) *(unsigned*)&g_P[nB + col] =
                        packbf2(acc[g][m][3] + bb.y, acc[g][m][2] + bb.x);
        }
    }
}

// ---------------- lstm: R9 structure (scalar cell) + bf16 P gathers ----------------
__global__ void __launch_bounds__(512, 1) lstm_kernel(const int* __restrict__ nbr) {
    extern __shared__ char smraw[];
    __nv_bfloat16* wsm  = (__nv_bfloat16*)smraw;          // 512 x BST
    __nv_bfloat16* hbuf = wsm + 512 * BST;                // 2 x 64 x BST
    int* snbr = (int*)(hbuf + 2 * 64 * BST);              // 64 x 16

    int tid = threadIdx.x, lane = tid & 31, warp = tid >> 5;
    int gid = lane >> 2, tig = lane & 3;
    int base = blockIdx.x * 64;

    // stage W_hh (bf16, k16-permuted) once
#pragma unroll
    for (int i = 0; i < 16; i++) {
        int idx = tid + i * 512;
        int n = idx >> 4, c = idx & 15;
        cpa16(wsm + n * BST + c * 8, g_WhhB + n * 128 + c * 8);
    }
    cpcommit();
    for (int i = tid; i < 64 * BST / 2; i += 512) ((unsigned*)hbuf)[i] = 0;  // zero h buf 0
#pragma unroll
    for (int i = 0; i < 2; i++) {
        int idx = tid + i * 512;
        int r = idx >> 4;
        snbr[idx] = (base + r < NN) ? nbr[(size_t)(base + r) * 16 + (idx & 15)] : 0;
    }
    asm volatile("cp.async.wait_group 0;");
    __syncthreads();

    const char* wbase = (const char*)wsm;
    int cb = warp * 8 + 2 * tig;                    // column pair base (per gate)
    int phys = (cb & ~15) | ((cb & 6) << 1) | ((cb & 8) >> 2);

    float cst[4][4];
#pragma unroll
    for (int m = 0; m < 4; m++)
#pragma unroll
        for (int s = 0; s < 4; s++) cst[m][s] = 0.f;

    float acc[4][4][4];   // [gate][m-tile][frag]
    // pre-gather step 0 gate init from bf16 P
#pragma unroll
    for (int m = 0; m < 4; m++) {
        const __nv_bfloat16* PA = g_P + (size_t)snbr[(m * 16 + gid) * 16 + 0] * 512;
        const __nv_bfloat16* PB = g_P + (size_t)snbr[(m * 16 + 8 + gid) * 16 + 0] * 512;
#pragma unroll
        for (int g = 0; g < 4; g++) {
            unsigned ua = *(const unsigned*)(PA + g * 128 + cb);
            unsigned ub = *(const unsigned*)(PB + g * 128 + cb);
            acc[g][m][0] = lo2f(ua); acc[g][m][1] = hi2f(ua);
            acc[g][m][2] = lo2f(ub); acc[g][m][3] = hi2f(ub);
        }
    }

    for (int t = 0; t < 16; t++) {
        const char* hc = (const char*)(hbuf + (t & 1) * 64 * BST);
        char*       hn = (char*)(hbuf + ((t + 1) & 1) * 64 * BST);

        // acc += h @ Whh^T  (bf16 m16n8k16)
#pragma unroll
        for (int kc = 0; kc < 8; kc++) {
            uint2 va[4], vb[4];
#pragma unroll
            for (int m = 0; m < 4; m++) {
                va[m] = *(const uint2*)(hc + (m * 16 + gid) * (BST * 2) + kc * 32 + tig * 8);
                vb[m] = *(const uint2*)(hc + (m * 16 + 8 + gid) * (BST * 2) + kc * 32 + tig * 8);
            }
#pragma unroll
            for (int g = 0; g < 4; g++) {
                uint2 b = *(const uint2*)(wbase + (g * 128 + warp * 8 + gid) * (BST * 2)
                                          + kc * 32 + tig * 8);
#pragma unroll
                for (int m = 0; m < 4; m++)
                    mma16(acc[g][m], va[m].x, vb[m].x, va[m].y, vb[m].y, b.x, b.y);
            }
        }

        // scalar cell update (tanh.approx.f32) + gather-ahead + bf16x2 h store
#pragma unroll
        for (int m = 0; m < 4; m++) {
            float hv[4];
#pragma unroll
            for (int s = 0; s < 4; s++) {
                float iv = siga(acc[0][m][s]);
                float fv = siga(acc[1][m][s]);
                float gv = tanha(acc[2][m][s]);
                float ov = siga(acc[3][m][s]);
                float c = fv * cst[m][s] + iv * gv;
                cst[m][s] = c;
                hv[s] = ov * tanha(c);
            }
            if (t < 15) {   // prefetch next step's gate init into freed acc regs
                const __nv_bfloat16* PA =
                    g_P + (size_t)snbr[(m * 16 + gid) * 16 + t + 1] * 512;
                const __nv_bfloat16* PB =
                    g_P + (size_t)snbr[(m * 16 + 8 + gid) * 16 + t + 1] * 512;
#pragma unroll
                for (int g = 0; g < 4; g++) {
                    unsigned ua = *(const unsigned*)(PA + g * 128 + cb);
                    unsigned ub = *(const unsigned*)(PB + g * 128 + cb);
                    acc[g][m][0] = lo2f(ua); acc[g][m][1] = hi2f(ua);
                    acc[g][m][2] = lo2f(ub); acc[g][m][3] = hi2f(ub);
                }
            }
            *(unsigned*)(hn + (m * 16 + gid) * (BST * 2) + phys * 2)     = packbf2(hv[1], hv[0]);
            *(unsigned*)(hn + (m * 16 + 8 + gid) * (BST * 2) + phys * 2) = packbf2(hv[3], hv[2]);
        }
        __syncthreads();
    }

    // final hidden in buffer 0; un-permute to g_Hn fp32
    const __nv_bfloat16* hf = hbuf;
    for (int i = tid; i < 64 * 128; i += 512) {
        int r = i >> 7, uu = i & 127;
        if (base + r < NN)
            g_Hn[(size_t)(base + r) * 128 + uu] = __bfloat162float(hf[r * BST + perm16(uu)]);
    }
}

// ---------------- out: o = x@Wself^T + hN@Wneigh^T + b  (+ ReLU / sigmoid) ----------------
template<int HOUT, int ACT>
__global__ void __launch_bounds__(512, 1) out_kernel(const float* __restrict__ xext, int sel,
                                                     float* __restrict__ oext, int osel) {
    extern __shared__ float sm[];
    float* xs = sm;
    float* h2 = xs + 64 * HSZ;
    float* ws = h2 + 64 * HSZ;
    float* wn = ws + HOUT * WFT;
    const float* x = sel ? g_H : xext;
    float* o = osel ? oext : g_H;
    int tid = threadIdx.x, lane = tid & 31, warp = tid >> 5;
    int wr = warp >> 2, cg = warp & 3, gid = lane >> 2, tig = lane & 3;
    int base = blockIdx.x * 64;
    int rowA = wr * 16 + gid, rowB = rowA + 8;
    bool vA = base + rowA < NN, vB = base + rowB < NN;

#pragma unroll
    for (int i = 0; i < 4; i++) {
        int idx = tid + i * 512;
        int r = idx >> 5, c = idx & 31;
        if (base + r < NN) {
            cpa16(xs + r * HSZ + c * 4, x    + (size_t)(base + r) * 128 + c * 4);
            cpa16(h2 + r * HSZ + c * 4, g_Hn + (size_t)(base + r) * 128 + c * 4);
        }
    }
#pragma unroll
    for (int i = 0; i < HOUT * 32 / 512; i++) {
        int idx = tid + i * 512;
        int n = idx >> 5, c = idx & 31;
        cpa16(ws + n * WFT + c * 4, g_Wself  + n * 128 + c * 4);
        cpa16(wn + n * WFT + c * 4, g_Wneigh + n * 128 + c * 4);
    }
    cpcommit();
    asm volatile("cp.async.wait_group 0;");
    __syncthreads();

    constexpr int T = HOUT / 32;
    float acc[T][4];
#pragma unroll
    for (int tt = 0; tt < T; tt++)
#pragma unroll
        for (int s = 0; s < 4; s++) acc[tt][s] = 0.f;

#pragma unroll
    for (int p = 0; p < 2; p++) {
        const float* As = p ? h2 : xs;
        const float* W  = p ? wn : ws;
#pragma unroll
        for (int kc = 0; kc < 16; kc++) {
            int kk = kc * 8;
            unsigned a0 = tf32u(As[rowA * HSZ + kk + tig]);
            unsigned a1 = tf32u(As[rowB * HSZ + kk + tig]);
            unsigned a2 = tf32u(As[rowA * HSZ + kk + tig + 4]);
            unsigned a3 = tf32u(As[rowB * HSZ + kk + tig + 4]);
#pragma unroll
            for (int tt = 0; tt < T; tt++) {
                float2 b = *(const float2*)&W[(cg * (HOUT / 4) + tt * 8 + gid) * WFT
                                              + kk + 2 * tig];
                mma8(acc[tt], a0, a1, a2, a3, __float_as_uint(b.x), __float_as_uint(b.y));
            }
        }
    }
#pragma unroll
    for (int tt = 0; tt < T; tt++)
#pragma unroll
        for (int s = 0; s < 4; s++) {
            int u = cg * (HOUT / 4) + tt * 8 + 2 * tig + (s & 1);
            float v = acc[tt][s] + g_bout[u];
            v = ACT ? sigf(v) : fmaxf(v, 0.f);
            int row = (s < 2) ? rowA : rowB;
            bool vv = (s < 2) ? vA : vB;
            if (vv) o[(size_t)(base + row) * HOUT + u] = v;
        }
}

// ---------------- launch ----------------
extern "C" void kernel_launch(void* const* d_in, const int* in_sizes, int n_in,
                              void* d_out, int out_size) {
    const float* feats = (const float*)d_in[0];
    const int*   nbr   = (const int*)d_in[1];

    const int PSM  = (512 * BST + 64 * BST) * 2;                     // 165888
    const int LSM  = 512 * BST * 2 + 2 * 64 * BST * 2 + 64 * 16 * 4; // 188416
    const int OSM1 = (2 * 64 * HSZ + 2 * 128 * WFT) * 4;             // 206848
    const int OSM2 = (2 * 64 * HSZ + 2 * 64 * WFT) * 4;              // 137216
    cudaFuncSetAttribute(proj_kernel,       cudaFuncAttributeMaxDynamicSharedMemorySize, PSM);
    cudaFuncSetAttribute(lstm_kernel,       cudaFuncAttributeMaxDynamicSharedMemorySize, LSM);
    cudaFuncSetAttribute(out_kernel<128,0>, cudaFuncAttributeMaxDynamicSharedMemorySize, OSM1);
    cudaFuncSetAttribute(out_kernel<64,1>,  cudaFuncAttributeMaxDynamicSharedMemorySize, OSM2);

    dim3 g(NBLK), b(512);

    // layer 1
    prep_kernel<<<256, 256>>>((const float*)d_in[2], (const float*)d_in[3],
                              (const float*)d_in[4], (const float*)d_in[5],
                              (const float*)d_in[6], (const float*)d_in[7],
                              (const float*)d_in[8], 128);
    proj_kernel<<<g, b, PSM>>>(feats, 0);
    lstm_kernel<<<g, b, LSM>>>(nbr);
    out_kernel<128, 0><<<g, b, OSM1>>>(feats, 0, nullptr, 0);

    // layer 2
    prep_kernel<<<256, 256>>>((const float*)d_in[9],  (const float*)d_in[10],
                              (const float*)d_in[11], (const float*)d_in[12],
                              (const float*)d_in[13], (const float*)d_in[14],
                              (const float*)d_in[15], 64);
    proj_kernel<<<g, b, PSM>>>(nullptr, 1);
    lstm_kernel<<<g, b, LSM>>>(nbr);
    out_kernel<64, 1><<<g, b, OSM2>>>(nullptr, 1, (float*)d_out, 1);
}